// round 1
// baseline (speedup 1.0000x reference)
#include <cuda_runtime.h>
#include <math.h>

// ---------------- problem constants ----------------
#define BB    4
#define TT    1024
#define DIM   2048
#define NH    16
#define NKV   4
#define DH    128
#define HID   8192
#define BT    (BB*TT)          // 4096 rows
#define KVD   (NKV*DH)         // 512

// ---------------- scratch (device globals; no allocation allowed) ----------
__device__ float g_a [BT*DIM];                       // rmsnorm1 out
__device__ float g_q [BT*DIM];                       // Q
__device__ float g_k [BT*KVD];                       // K
__device__ float g_v [BT*KVD];                       // V
__device__ float g_s [(size_t)BB*NH*TT*TT];          // attention scores/probs (256 MB)
__device__ float g_y [BT*DIM];                       // attention out
__device__ float g_x1[BT*DIM];                       // x + y@wo
__device__ float g_b [BT*DIM];                       // rmsnorm2 out
__device__ float g_h1[(size_t)BT*HID];               // b@w1 (then silu*h2)
__device__ float g_h2[(size_t)BT*HID];               // b@w2

// ---------------- block reductions ----------------
__device__ __forceinline__ float blockReduceSum(float v) {
    __shared__ float sh[32];
    int lane = threadIdx.x & 31, w = threadIdx.x >> 5;
    #pragma unroll
    for (int o = 16; o > 0; o >>= 1) v += __shfl_xor_sync(0xffffffffu, v, o);
    if (lane == 0) sh[w] = v;
    __syncthreads();
    if (w == 0) {
        v = (lane < (int)(blockDim.x >> 5)) ? sh[lane] : 0.f;
        #pragma unroll
        for (int o = 4; o > 0; o >>= 1) v += __shfl_xor_sync(0xffffffffu, v, o);
        if (lane == 0) sh[0] = v;
    }
    __syncthreads();
    float r = sh[0];
    __syncthreads();
    return r;
}

__device__ __forceinline__ float blockReduceMax(float v) {
    __shared__ float sh[32];
    int lane = threadIdx.x & 31, w = threadIdx.x >> 5;
    #pragma unroll
    for (int o = 16; o > 0; o >>= 1) v = fmaxf(v, __shfl_xor_sync(0xffffffffu, v, o));
    if (lane == 0) sh[w] = v;
    __syncthreads();
    if (w == 0) {
        v = (lane < (int)(blockDim.x >> 5)) ? sh[lane] : -3.4e38f;
        #pragma unroll
        for (int o = 4; o > 0; o >>= 1) v = fmaxf(v, __shfl_xor_sync(0xffffffffu, v, o));
        if (lane == 0) sh[0] = v;
    }
    __syncthreads();
    float r = sh[0];
    __syncthreads();
    return r;
}

// ---------------- rmsnorm ----------------
__global__ void __launch_bounds__(256) k_rmsnorm(const float* __restrict__ x,
                                                 const float* __restrict__ w,
                                                 float* __restrict__ o) {
    const int row = blockIdx.x;
    const float4* xr = (const float4*)(x + (size_t)row * DIM);
    float4 v0 = xr[threadIdx.x];
    float4 v1 = xr[threadIdx.x + 256];
    float ss = v0.x*v0.x + v0.y*v0.y + v0.z*v0.z + v0.w*v0.w
             + v1.x*v1.x + v1.y*v1.y + v1.z*v1.z + v1.w*v1.w;
    ss = blockReduceSum(ss);
    float scale = rsqrtf(ss * (1.0f/DIM) + 1e-5f);
    const float4* wr = (const float4*)w;
    float4* orow = (float4*)(o + (size_t)row * DIM);
    float4 w0 = wr[threadIdx.x], w1v = wr[threadIdx.x + 256];
    float4 r0, r1;
    r0.x = v0.x*scale*w0.x; r0.y = v0.y*scale*w0.y; r0.z = v0.z*scale*w0.z; r0.w = v0.w*scale*w0.w;
    r1.x = v1.x*scale*w1v.x; r1.y = v1.y*scale*w1v.y; r1.z = v1.z*scale*w1v.z; r1.w = v1.w*scale*w1v.w;
    orow[threadIdx.x] = r0;
    orow[threadIdx.x + 256] = r1;
}

// ---------------- rope (in place), X layout [BT, nheads, 128] ----------------
__global__ void k_rope(float* __restrict__ X, int nheads, int total) {
    int idx = blockIdx.x * blockDim.x + threadIdx.x;
    if (idx >= total) return;
    int i  = idx & 63;
    int h  = (idx >> 6) % nheads;
    int bt = idx / (64 * nheads);
    int t  = bt & (TT - 1);
    float inv = powf(10000.0f, -(float)i * (1.0f/64.0f));
    float ang = (float)t * inv;
    float s, c;
    sincosf(ang, &s, &c);
    float* base = X + ((size_t)bt * nheads + h) * DH + i;
    float x1v = base[0];
    float x2v = base[64];
    base[0]  = x1v * c - x2v * s;
    base[64] = x1v * s + x2v * c;
}

// ---------------- generic 128x128x8 SGEMM body ----------------
// BT_LAYOUT=false: B is [K,N] row-major (NN).  true: B is [N,K] row-major (NT).
template<bool BT_LAYOUT>
__device__ __forceinline__ void gemm_body(const float* __restrict__ A,
                                          const float* __restrict__ B,
                                          float* __restrict__ C,
                                          const float* __restrict__ R,
                                          int K, int lda, int ldb, int ldc) {
    __shared__ float As[8][128];
    __shared__ float Bs[8][128];
    const int tid = threadIdx.x;
    const int tx = tid & 15, ty = tid >> 4;
    const int bm = blockIdx.y * 128, bn = blockIdx.x * 128;

    const int a_row = tid >> 1;            // 0..127
    const int a_col = (tid & 1) * 4;       // 0 or 4
    const float* Ap = A + (size_t)(bm + a_row) * lda + a_col;

    const float* Bp;
    int b_i0, b_i1;
    if (BT_LAYOUT) {
        b_i0 = tid >> 1;                   // n: 0..127
        b_i1 = (tid & 1) * 4;              // k: 0 or 4
        Bp = B + (size_t)(bn + b_i0) * ldb + b_i1;
    } else {
        b_i0 = tid >> 5;                   // k: 0..7
        b_i1 = (tid & 31) * 4;             // n: 0..124
        Bp = B + (size_t)b_i0 * ldb + bn + b_i1;
    }

    float acc[8][8];
    #pragma unroll
    for (int i = 0; i < 8; i++)
        #pragma unroll
        for (int j = 0; j < 8; j++) acc[i][j] = 0.f;

    for (int k0 = 0; k0 < K; k0 += 8) {
        float4 av = *(const float4*)Ap;
        As[a_col+0][a_row] = av.x;
        As[a_col+1][a_row] = av.y;
        As[a_col+2][a_row] = av.z;
        As[a_col+3][a_row] = av.w;
        float4 bv = *(const float4*)Bp;
        if (BT_LAYOUT) {
            Bs[b_i1+0][b_i0] = bv.x;
            Bs[b_i1+1][b_i0] = bv.y;
            Bs[b_i1+2][b_i0] = bv.z;
            Bs[b_i1+3][b_i0] = bv.w;
            Bp += 8;
        } else {
            *(float4*)&Bs[b_i0][b_i1] = bv;
            Bp += (size_t)8 * ldb;
        }
        Ap += 8;
        __syncthreads();
        #pragma unroll
        for (int kk = 0; kk < 8; kk++) {
            float4 a0 = *(const float4*)&As[kk][ty*8];
            float4 a1 = *(const float4*)&As[kk][ty*8+4];
            float4 b0 = *(const float4*)&Bs[kk][tx*8];
            float4 b1 = *(const float4*)&Bs[kk][tx*8+4];
            float ra[8] = {a0.x,a0.y,a0.z,a0.w,a1.x,a1.y,a1.z,a1.w};
            float rb[8] = {b0.x,b0.y,b0.z,b0.w,b1.x,b1.y,b1.z,b1.w};
            #pragma unroll
            for (int i = 0; i < 8; i++)
                #pragma unroll
                for (int j = 0; j < 8; j++)
                    acc[i][j] = fmaf(ra[i], rb[j], acc[i][j]);
        }
        __syncthreads();
    }

    #pragma unroll
    for (int i = 0; i < 8; i++) {
        size_t off = (size_t)(bm + ty*8 + i) * ldc + bn + tx*8;
        if (R) {
            #pragma unroll
            for (int j = 0; j < 8; j++) acc[i][j] += R[off + j];
        }
        float4 c0 = make_float4(acc[i][0], acc[i][1], acc[i][2], acc[i][3]);
        float4 c1 = make_float4(acc[i][4], acc[i][5], acc[i][6], acc[i][7]);
        *(float4*)(C + off)     = c0;
        *(float4*)(C + off + 4) = c1;
    }
}

__global__ void __launch_bounds__(256) k_gemm_nn(const float* __restrict__ A,
                                                 const float* __restrict__ B,
                                                 float* __restrict__ C,
                                                 const float* __restrict__ R,
                                                 int K, int lda, int ldb, int ldc) {
    gemm_body<false>(A, B, C, R, K, lda, ldb, ldc);
}

// scores: S[z] = Q_bh @ K_bkv^T     z = b*16 + h
__global__ void __launch_bounds__(256) k_gemm_scores(const float* __restrict__ q,
                                                     const float* __restrict__ k,
                                                     float* __restrict__ s) {
    int z = blockIdx.z;
    int bb = z >> 4, h = z & 15, kv = h >> 2;
    gemm_body<true>(q + (size_t)bb*TT*DIM + h*DH,
                    k + (size_t)bb*TT*KVD + kv*DH,
                    s + (size_t)z*TT*TT, nullptr,
                    DH, DIM, KVD, TT);
}

// y_bh = P[z] @ V_bkv
__global__ void __launch_bounds__(256) k_gemm_pv(const float* __restrict__ s,
                                                 const float* __restrict__ v,
                                                 float* __restrict__ y) {
    int z = blockIdx.z;
    int bb = z >> 4, h = z & 15, kv = h >> 2;
    gemm_body<false>(s + (size_t)z*TT*TT,
                     v + (size_t)bb*TT*KVD + kv*DH,
                     y + (size_t)bb*TT*DIM + h*DH, nullptr,
                     TT, TT, KVD, DIM);
}

// ---------------- causal softmax over score rows (scale folded in) ----------
__global__ void __launch_bounds__(256) k_softmax(float* __restrict__ S) {
    const size_t row = blockIdx.x;               // 0 .. B*H*T-1
    const int t = blockIdx.x & (TT - 1);
    float* p = S + row * TT;
    const int n = t + 1;
    const float scale = 0.08838834764831845f;    // 1/sqrt(128)
    const int tid = threadIdx.x;

    float v[4];
    float mx = -3.4e38f;
    #pragma unroll
    for (int u = 0; u < 4; u++) {
        int i = tid + u * 256;
        v[u] = (i < n) ? p[i] * scale : -3.4e38f;
        mx = fmaxf(mx, v[u]);
    }
    mx = blockReduceMax(mx);

    float e[4];
    float lsum = 0.f;
    #pragma unroll
    for (int u = 0; u < 4; u++) {
        int i = tid + u * 256;
        e[u] = (i < n) ? __expf(v[u] - mx) : 0.f;
        lsum += e[u];
    }
    float s = blockReduceSum(lsum);
    float inv = 1.0f / s;
    #pragma unroll
    for (int u = 0; u < 4; u++) p[tid + u * 256] = e[u] * inv;
}

// ---------------- silu(h1) * h2 -> h1 ----------------
__global__ void __launch_bounds__(256) k_silu_mul(float4* __restrict__ h1,
                                                  const float4* __restrict__ h2,
                                                  int n4) {
    int i = blockIdx.x * blockDim.x + threadIdx.x;
    if (i >= n4) return;
    float4 a = h1[i], b = h2[i];
    a.x = a.x / (1.f + expf(-a.x)) * b.x;
    a.y = a.y / (1.f + expf(-a.y)) * b.y;
    a.z = a.z / (1.f + expf(-a.z)) * b.z;
    a.w = a.w / (1.f + expf(-a.w)) * b.w;
    h1[i] = a;
}

// ---------------- launch ----------------
extern "C" void kernel_launch(void* const* d_in, const int* in_sizes, int n_in,
                              void* d_out, int out_size) {
    const float* x   = (const float*)d_in[0];
    const float* anw = (const float*)d_in[1];
    const float* fnw = (const float*)d_in[2];
    const float* wq  = (const float*)d_in[3];
    const float* wk  = (const float*)d_in[4];
    const float* wv  = (const float*)d_in[5];
    const float* wo  = (const float*)d_in[6];
    const float* w1  = (const float*)d_in[7];
    const float* w2  = (const float*)d_in[8];
    const float* w3  = (const float*)d_in[9];
    float* out = (float*)d_out;

    float *a, *q, *k, *v, *s, *y, *x1, *b, *h1, *h2;
    cudaGetSymbolAddress((void**)&a,  g_a);
    cudaGetSymbolAddress((void**)&q,  g_q);
    cudaGetSymbolAddress((void**)&k,  g_k);
    cudaGetSymbolAddress((void**)&v,  g_v);
    cudaGetSymbolAddress((void**)&s,  g_s);
    cudaGetSymbolAddress((void**)&y,  g_y);
    cudaGetSymbolAddress((void**)&x1, g_x1);
    cudaGetSymbolAddress((void**)&b,  g_b);
    cudaGetSymbolAddress((void**)&h1, g_h1);
    cudaGetSymbolAddress((void**)&h2, g_h2);

    // 1. a = rmsnorm(x) * attn_norm_w
    k_rmsnorm<<<BT, 256>>>(x, anw, a);
    // 2-4. q/k/v projections
    k_gemm_nn<<<dim3(DIM/128, BT/128), 256>>>(a, wq, q, nullptr, DIM, DIM, DIM, DIM);
    k_gemm_nn<<<dim3(KVD/128, BT/128), 256>>>(a, wk, k, nullptr, DIM, DIM, KVD, KVD);
    k_gemm_nn<<<dim3(KVD/128, BT/128), 256>>>(a, wv, v, nullptr, DIM, DIM, KVD, KVD);
    // 5-6. rope
    k_rope<<<(BT*NH*64)/256, 256>>>(q, NH, BT*NH*64);
    k_rope<<<(BT*NKV*64)/256, 256>>>(k, NKV, BT*NKV*64);
    // 7. scores = Q @ K^T   (batched over B*H)
    k_gemm_scores<<<dim3(TT/128, TT/128, BB*NH), 256>>>(q, k, s);
    // 8. causal softmax (scale applied here)
    k_softmax<<<BB*NH*TT, 256>>>(s);
    // 9. y = P @ V
    k_gemm_pv<<<dim3(1, TT/128, BB*NH), 256>>>(s, v, y);
    // 10. x1 = x + y @ wo
    k_gemm_nn<<<dim3(DIM/128, BT/128), 256>>>(y, wo, x1, x, DIM, DIM, DIM, DIM);
    // 11. b = rmsnorm(x1) * ff_norm_w
    k_rmsnorm<<<BT, 256>>>(x1, fnw, b);
    // 12-13. MLP up projections
    k_gemm_nn<<<dim3(HID/128, BT/128), 256>>>(b, w1, h1, nullptr, DIM, DIM, HID, HID);
    k_gemm_nn<<<dim3(HID/128, BT/128), 256>>>(b, w2, h2, nullptr, DIM, DIM, HID, HID);
    // 14. h1 = silu(h1) * h2
    {
        int n4 = (int)((size_t)BT * HID / 4);
        k_silu_mul<<<(n4 + 255) / 256, 256>>>((float4*)h1, (const float4*)h2, n4);
    }
    // 15. out = x1 + h1 @ w3
    k_gemm_nn<<<dim3(DIM/128, BT/128), 256>>>(h1, w3, out, x1, HID, HID, DIM, DIM);
}

// round 4
// speedup vs baseline: 1.2462x; 1.2462x over previous
#include <cuda_runtime.h>
#include <math.h>
#include <stdint.h>

// ---------------- problem constants ----------------
#define BB    4
#define TT    1024
#define DIM   2048
#define NH    16
#define NKV   4
#define DH    128
#define HID   8192
#define BT    (BB*TT)          // 4096 rows
#define KVD   (NKV*DH)         // 512

#define BK    16
#define KPAD  20

// ---------------- scratch (device globals; no allocation allowed) ----------
__device__ float g_a [BT*DIM];
__device__ float g_q [BT*DIM];
__device__ float g_k [BT*KVD];
__device__ float g_v [BT*KVD];
__device__ float g_s [(size_t)BB*NH*TT*TT];          // scores/probs (256 MB)
__device__ float g_y [BT*DIM];
__device__ float g_x1[BT*DIM];
__device__ float g_b [BT*DIM];
__device__ float g_h1[(size_t)BT*HID];
__device__ float g_h2[(size_t)BT*HID];

// ---------------- helpers ----------------
__device__ __forceinline__ uint32_t f2tf(float f) {
    uint32_t u;
    asm("cvt.rna.tf32.f32 %0, %1;" : "=r"(u) : "f"(f));
    return u;
}

__device__ __forceinline__ void mma8(float* d, const uint32_t* a, const uint32_t* b) {
    asm volatile(
        "mma.sync.aligned.m16n8k8.row.col.f32.tf32.tf32.f32 "
        "{%0,%1,%2,%3},{%4,%5,%6,%7},{%8,%9},{%0,%1,%2,%3};"
        : "+f"(d[0]), "+f"(d[1]), "+f"(d[2]), "+f"(d[3])
        : "r"(a[0]), "r"(a[1]), "r"(a[2]), "r"(a[3]), "r"(b[0]), "r"(b[1]));
}

__device__ __forceinline__ float blockReduceSum(float v) {
    __shared__ float sh[32];
    int lane = threadIdx.x & 31, w = threadIdx.x >> 5;
    #pragma unroll
    for (int o = 16; o > 0; o >>= 1) v += __shfl_xor_sync(0xffffffffu, v, o);
    if (lane == 0) sh[w] = v;
    __syncthreads();
    if (w == 0) {
        v = (lane < (int)(blockDim.x >> 5)) ? sh[lane] : 0.f;
        #pragma unroll
        for (int o = 4; o > 0; o >>= 1) v += __shfl_xor_sync(0xffffffffu, v, o);
        if (lane == 0) sh[0] = v;
    }
    __syncthreads();
    float r = sh[0];
    __syncthreads();
    return r;
}

__device__ __forceinline__ float blockReduceMax(float v) {
    __shared__ float sh[32];
    int lane = threadIdx.x & 31, w = threadIdx.x >> 5;
    #pragma unroll
    for (int o = 16; o > 0; o >>= 1) v = fmaxf(v, __shfl_xor_sync(0xffffffffu, v, o));
    if (lane == 0) sh[w] = v;
    __syncthreads();
    if (w == 0) {
        v = (lane < (int)(blockDim.x >> 5)) ? sh[lane] : -3.4e38f;
        #pragma unroll
        for (int o = 4; o > 0; o >>= 1) v = fmaxf(v, __shfl_xor_sync(0xffffffffu, v, o));
        if (lane == 0) sh[0] = v;
    }
    __syncthreads();
    float r = sh[0];
    __syncthreads();
    return r;
}

// ---------------- tf32x3 tensor-core GEMM ----------------
// C[128x128 tile] = A[M,K] * B  (+R)
// BT_LAYOUT=false: B is [K,N] row-major (NN). true: B is [N,K] row-major (NT).
template<bool BT_LAYOUT>
__device__ __forceinline__ void mma_gemm(const float* __restrict__ A,
                                         const float* __restrict__ B,
                                         float* __restrict__ C,
                                         const float* __restrict__ R,
                                         int K, int lda, int ldb, int ldc) {
    __shared__ uint32_t Ah[128][KPAD], Al[128][KPAD];
    __shared__ uint32_t Bh[128][KPAD], Bl[128][KPAD];

    const int tid  = threadIdx.x;
    const int lane = tid & 31;
    const int wid  = tid >> 5;
    const int wr   = wid >> 1;        // 0..3 -> rows wr*32
    const int wc   = wid & 1;         // 0..1 -> cols wc*64
    const int g    = lane >> 2;       // 0..7
    const int t    = lane & 3;        // 0..3
    const int bm   = blockIdx.y * 128;
    const int bn   = blockIdx.x * 128;

    // global load indices
    const int ar = tid >> 2;          // 0..63
    const int ac = (tid & 3) * 4;     // 0,4,8,12
    const int bnn_n = tid & 127;      // 0..127  (NN B loads)
    const int bnn_k = (tid >> 7) * 8; // 0 or 8

    float4 pa0, pa1, pb0, pb1;
    float  pn[8];

    // ---- prefetch k0=0 ----
    {
        pa0 = *(const float4*)(A + (size_t)(bm + ar)      * lda + ac);
        pa1 = *(const float4*)(A + (size_t)(bm + ar + 64) * lda + ac);
        if (BT_LAYOUT) {
            pb0 = *(const float4*)(B + (size_t)(bn + ar)      * ldb + ac);
            pb1 = *(const float4*)(B + (size_t)(bn + ar + 64) * ldb + ac);
        } else {
            #pragma unroll
            for (int j = 0; j < 8; j++)
                pn[j] = B[(size_t)(bnn_k + j) * ldb + bn + bnn_n];
        }
    }

    float acc[2][8][4];
    #pragma unroll
    for (int m = 0; m < 2; m++)
        #pragma unroll
        for (int n = 0; n < 8; n++)
            #pragma unroll
            for (int i = 0; i < 4; i++) acc[m][n][i] = 0.f;

    for (int k0 = 0; k0 < K; k0 += BK) {
        // ---- store prefetched tile to smem (with tf32 hi/lo split) ----
        {
            float va[2][4] = {{pa0.x, pa0.y, pa0.z, pa0.w}, {pa1.x, pa1.y, pa1.z, pa1.w}};
            #pragma unroll
            for (int i = 0; i < 2; i++)
                #pragma unroll
                for (int j = 0; j < 4; j++) {
                    uint32_t hi = f2tf(va[i][j]);
                    Ah[ar + i*64][ac + j] = hi;
                    Al[ar + i*64][ac + j] = f2tf(va[i][j] - __uint_as_float(hi));
                }
            if (BT_LAYOUT) {
                float vb[2][4] = {{pb0.x, pb0.y, pb0.z, pb0.w}, {pb1.x, pb1.y, pb1.z, pb1.w}};
                #pragma unroll
                for (int i = 0; i < 2; i++)
                    #pragma unroll
                    for (int j = 0; j < 4; j++) {
                        uint32_t hi = f2tf(vb[i][j]);
                        Bh[ar + i*64][ac + j] = hi;
                        Bl[ar + i*64][ac + j] = f2tf(vb[i][j] - __uint_as_float(hi));
                    }
            } else {
                #pragma unroll
                for (int j = 0; j < 8; j++) {
                    uint32_t hi = f2tf(pn[j]);
                    Bh[bnn_n][bnn_k + j] = hi;
                    Bl[bnn_n][bnn_k + j] = f2tf(pn[j] - __uint_as_float(hi));
                }
            }
        }
        __syncthreads();

        // ---- prefetch next tile ----
        if (k0 + BK < K) {
            int kn = k0 + BK;
            pa0 = *(const float4*)(A + (size_t)(bm + ar)      * lda + kn + ac);
            pa1 = *(const float4*)(A + (size_t)(bm + ar + 64) * lda + kn + ac);
            if (BT_LAYOUT) {
                pb0 = *(const float4*)(B + (size_t)(bn + ar)      * ldb + kn + ac);
                pb1 = *(const float4*)(B + (size_t)(bn + ar + 64) * ldb + kn + ac);
            } else {
                #pragma unroll
                for (int j = 0; j < 8; j++)
                    pn[j] = B[(size_t)(kn + bnn_k + j) * ldb + bn + bnn_n];
            }
        }

        // ---- compute ----
        #pragma unroll
        for (int kk = 0; kk < BK; kk += 8) {
            uint32_t ah[2][4], al[2][4];
            #pragma unroll
            for (int m = 0; m < 2; m++) {
                int r0 = wr*32 + m*16 + g;
                ah[m][0] = Ah[r0    ][kk + t];
                ah[m][1] = Ah[r0 + 8][kk + t];
                ah[m][2] = Ah[r0    ][kk + t + 4];
                ah[m][3] = Ah[r0 + 8][kk + t + 4];
                al[m][0] = Al[r0    ][kk + t];
                al[m][1] = Al[r0 + 8][kk + t];
                al[m][2] = Al[r0    ][kk + t + 4];
                al[m][3] = Al[r0 + 8][kk + t + 4];
            }
            #pragma unroll
            for (int n = 0; n < 8; n++) {
                int n0 = wc*64 + n*8 + g;
                uint32_t bh[2], bl[2];
                bh[0] = Bh[n0][kk + t];
                bh[1] = Bh[n0][kk + t + 4];
                bl[0] = Bl[n0][kk + t];
                bl[1] = Bl[n0][kk + t + 4];
                #pragma unroll
                for (int m = 0; m < 2; m++) {
                    mma8(acc[m][n], ah[m], bh);
                    mma8(acc[m][n], ah[m], bl);
                    mma8(acc[m][n], al[m], bh);
                }
            }
        }
        __syncthreads();
    }

    // ---- epilogue ----
    #pragma unroll
    for (int m = 0; m < 2; m++) {
        int row = bm + wr*32 + m*16 + g;
        #pragma unroll
        for (int n = 0; n < 8; n++) {
            int col = bn + wc*64 + n*8 + t*2;
            size_t o0 = (size_t)row       * ldc + col;
            size_t o1 = (size_t)(row + 8) * ldc + col;
            float2 v0 = make_float2(acc[m][n][0], acc[m][n][1]);
            float2 v1 = make_float2(acc[m][n][2], acc[m][n][3]);
            if (R) {
                float2 r0 = *(const float2*)(R + o0);
                float2 r1 = *(const float2*)(R + o1);
                v0.x += r0.x; v0.y += r0.y;
                v1.x += r1.x; v1.y += r1.y;
            }
            *(float2*)(C + o0) = v0;
            *(float2*)(C + o1) = v1;
        }
    }
}

__global__ void __launch_bounds__(256) k_mma_nn(const float* __restrict__ A,
                                                const float* __restrict__ B,
                                                float* __restrict__ C,
                                                const float* __restrict__ R,
                                                int K, int lda, int ldb, int ldc) {
    mma_gemm<false>(A, B, C, R, K, lda, ldb, ldc);
}

// scores: S[z] = Q_bh @ K_bkv^T  (causal: skip fully-masked upper tiles)
__global__ void __launch_bounds__(256) k_mma_scores(const float* __restrict__ q,
                                                    const float* __restrict__ k,
                                                    float* __restrict__ s) {
    if (blockIdx.x * 128 > blockIdx.y * 128 + 127) return;  // strictly upper tile
    int z = blockIdx.z;
    int bb = z >> 4, h = z & 15, kv = h >> 2;
    mma_gemm<true>(q + (size_t)bb*TT*DIM + h*DH,
                   k + (size_t)bb*TT*KVD + kv*DH,
                   s + (size_t)z*TT*TT, nullptr,
                   DH, DIM, KVD, TT);
}

// y_bh = P[z] @ V_bkv
__global__ void __launch_bounds__(256) k_mma_pv(const float* __restrict__ s,
                                                const float* __restrict__ v,
                                                float* __restrict__ y) {
    int z = blockIdx.z;
    int bb = z >> 4, h = z & 15, kv = h >> 2;
    mma_gemm<false>(s + (size_t)z*TT*TT,
                    v + (size_t)bb*TT*KVD + kv*DH,
                    y + (size_t)bb*TT*DIM + h*DH, nullptr,
                    TT, TT, KVD, DIM);
}

// ---------------- rmsnorm ----------------
__global__ void __launch_bounds__(256) k_rmsnorm(const float* __restrict__ x,
                                                 const float* __restrict__ w,
                                                 float* __restrict__ o) {
    const int row = blockIdx.x;
    const float4* xr = (const float4*)(x + (size_t)row * DIM);
    float4 v0 = xr[threadIdx.x];
    float4 v1 = xr[threadIdx.x + 256];
    float ss = v0.x*v0.x + v0.y*v0.y + v0.z*v0.z + v0.w*v0.w
             + v1.x*v1.x + v1.y*v1.y + v1.z*v1.z + v1.w*v1.w;
    ss = blockReduceSum(ss);
    float scale = rsqrtf(ss * (1.0f/DIM) + 1e-5f);
    const float4* wr = (const float4*)w;
    float4* orow = (float4*)(o + (size_t)row * DIM);
    float4 w0 = wr[threadIdx.x], w1v = wr[threadIdx.x + 256];
    float4 r0, r1;
    r0.x = v0.x*scale*w0.x; r0.y = v0.y*scale*w0.y; r0.z = v0.z*scale*w0.z; r0.w = v0.w*scale*w0.w;
    r1.x = v1.x*scale*w1v.x; r1.y = v1.y*scale*w1v.y; r1.z = v1.z*scale*w1v.z; r1.w = v1.w*scale*w1v.w;
    orow[threadIdx.x] = r0;
    orow[threadIdx.x + 256] = r1;
}

// ---------------- rope (in place), X layout [BT, nheads, 128] ----------------
__global__ void k_rope(float* __restrict__ X, int nheads, int total) {
    int idx = blockIdx.x * blockDim.x + threadIdx.x;
    if (idx >= total) return;
    int i  = idx & 63;
    int h  = (idx >> 6) % nheads;
    int bt = idx / (64 * nheads);
    int t  = bt & (TT - 1);
    float inv = powf(10000.0f, -(float)i * (1.0f/64.0f));
    float ang = (float)t * inv;
    float s, c;
    sincosf(ang, &s, &c);
    float* base = X + ((size_t)bt * nheads + h) * DH + i;
    float x1v = base[0];
    float x2v = base[64];
    base[0]  = x1v * c - x2v * s;
    base[64] = x1v * s + x2v * c;
}

// ---------------- causal softmax (scale folded in) ----------------
__global__ void __launch_bounds__(256) k_softmax(float* __restrict__ S) {
    const size_t row = blockIdx.x;
    const int t = blockIdx.x & (TT - 1);
    float* p = S + row * TT;
    const int n = t + 1;
    const float scale = 0.08838834764831845f;    // 1/sqrt(128)
    const int tid = threadIdx.x;

    float v[4];
    float mx = -3.4e38f;
    #pragma unroll
    for (int u = 0; u < 4; u++) {
        int i = tid + u * 256;
        v[u] = (i < n) ? p[i] * scale : -3.4e38f;
        mx = fmaxf(mx, v[u]);
    }
    mx = blockReduceMax(mx);

    float e[4];
    float lsum = 0.f;
    #pragma unroll
    for (int u = 0; u < 4; u++) {
        int i = tid + u * 256;
        e[u] = (i < n) ? __expf(v[u] - mx) : 0.f;
        lsum += e[u];
    }
    float s = blockReduceSum(lsum);
    float inv = 1.0f / s;
    #pragma unroll
    for (int u = 0; u < 4; u++) p[tid + u * 256] = e[u] * inv;
}

// ---------------- silu(h1) * h2 -> h1 ----------------
__global__ void __launch_bounds__(256) k_silu_mul(float4* __restrict__ h1,
                                                  const float4* __restrict__ h2,
                                                  int n4) {
    int i = blockIdx.x * blockDim.x + threadIdx.x;
    if (i >= n4) return;
    float4 a = h1[i], b = h2[i];
    a.x = a.x / (1.f + expf(-a.x)) * b.x;
    a.y = a.y / (1.f + expf(-a.y)) * b.y;
    a.z = a.z / (1.f + expf(-a.z)) * b.z;
    a.w = a.w / (1.f + expf(-a.w)) * b.w;
    h1[i] = a;
}

// ---------------- launch ----------------
extern "C" void kernel_launch(void* const* d_in, const int* in_sizes, int n_in,
                              void* d_out, int out_size) {
    const float* x   = (const float*)d_in[0];
    const float* anw = (const float*)d_in[1];
    const float* fnw = (const float*)d_in[2];
    const float* wq  = (const float*)d_in[3];
    const float* wk  = (const float*)d_in[4];
    const float* wv  = (const float*)d_in[5];
    const float* wo  = (const float*)d_in[6];
    const float* w1  = (const float*)d_in[7];
    const float* w2  = (const float*)d_in[8];
    const float* w3  = (const float*)d_in[9];
    float* out = (float*)d_out;

    float *a, *q, *k, *v, *s, *y, *x1, *b, *h1, *h2;
    cudaGetSymbolAddress((void**)&a,  g_a);
    cudaGetSymbolAddress((void**)&q,  g_q);
    cudaGetSymbolAddress((void**)&k,  g_k);
    cudaGetSymbolAddress((void**)&v,  g_v);
    cudaGetSymbolAddress((void**)&s,  g_s);
    cudaGetSymbolAddress((void**)&y,  g_y);
    cudaGetSymbolAddress((void**)&x1, g_x1);
    cudaGetSymbolAddress((void**)&b,  g_b);
    cudaGetSymbolAddress((void**)&h1, g_h1);
    cudaGetSymbolAddress((void**)&h2, g_h2);

    // 1. a = rmsnorm(x) * attn_norm_w
    k_rmsnorm<<<BT, 256>>>(x, anw, a);
    // 2-4. q/k/v projections
    k_mma_nn<<<dim3(DIM/128, BT/128), 256>>>(a, wq, q, nullptr, DIM, DIM, DIM, DIM);
    k_mma_nn<<<dim3(KVD/128, BT/128), 256>>>(a, wk, k, nullptr, DIM, DIM, KVD, KVD);
    k_mma_nn<<<dim3(KVD/128, BT/128), 256>>>(a, wv, v, nullptr, DIM, DIM, KVD, KVD);
    // 5-6. rope
    k_rope<<<(BT*NH*64)/256, 256>>>(q, NH, BT*NH*64);
    k_rope<<<(BT*NKV*64)/256, 256>>>(k, NKV, BT*NKV*64);
    // 7. scores = Q @ K^T (batched over B*H, causal-skip upper tiles)
    k_mma_scores<<<dim3(TT/128, TT/128, BB*NH), 256>>>(q, k, s);
    // 8. causal softmax
    k_softmax<<<BB*NH*TT, 256>>>(s);
    // 9. y = P @ V
    k_mma_pv<<<dim3(1, TT/128, BB*NH), 256>>>(s, v, y);
    // 10. x1 = x + y @ wo
    k_mma_nn<<<dim3(DIM/128, BT/128), 256>>>(y, wo, x1, x, DIM, DIM, DIM, DIM);
    // 11. b = rmsnorm(x1) * ff_norm_w
    k_rmsnorm<<<BT, 256>>>(x1, fnw, b);
    // 12-13. MLP up projections
    k_mma_nn<<<dim3(HID/128, BT/128), 256>>>(b, w1, h1, nullptr, DIM, DIM, HID, HID);
    k_mma_nn<<<dim3(HID/128, BT/128), 256>>>(b, w2, h2, nullptr, DIM, DIM, HID, HID);
    // 14. h1 = silu(h1) * h2
    {
        int n4 = (int)((size_t)BT * HID / 4);
        k_silu_mul<<<(n4 + 255) / 256, 256>>>((float4*)h1, (const float4*)h2, n4);
    }
    // 15. out = x1 + h1 @ w3
    k_mma_nn<<<dim3(DIM/128, BT/128), 256>>>(h1, w3, out, x1, HID, HID, DIM, DIM);
}

// round 7
// speedup vs baseline: 1.7385x; 1.3950x over previous
#include <cuda_runtime.h>
#include <cuda_bf16.h>
#include <math.h>
#include <stdint.h>

// ---------------- problem constants ----------------
#define BB    4
#define TT    1024
#define DIM   2048
#define NH    16
#define NKV   4
#define DH    128
#define HID   8192
#define BT    (BB*TT)          // 4096 rows
#define KVD   (NKV*DH)         // 512

#define BK    32
#define SKP   40               // smem row stride in halves (32 + 8 pad)

// ---------------- fp32 activation scratch ----------------
__device__ float g_a [BT*DIM];
__device__ float g_q [BT*DIM];
__device__ float g_k [BT*KVD];
__device__ float g_v [BT*KVD];
__device__ float g_s [(size_t)BB*NH*TT*TT];          // scores/probs (256 MB)
__device__ float g_y [BT*DIM];
__device__ float g_x1[BT*DIM];
__device__ float g_b [BT*DIM];
__device__ float g_h1[(size_t)BT*HID];
__device__ float g_h2[(size_t)BT*HID];

// ---------------- transposed bf16 hi/lo weights [N][K] ----------------
__device__ __nv_bfloat16 g_wqT_h[(size_t)DIM*DIM],  g_wqT_l[(size_t)DIM*DIM];
__device__ __nv_bfloat16 g_wkT_h[(size_t)KVD*DIM],  g_wkT_l[(size_t)KVD*DIM];
__device__ __nv_bfloat16 g_wvT_h[(size_t)KVD*DIM],  g_wvT_l[(size_t)KVD*DIM];
__device__ __nv_bfloat16 g_woT_h[(size_t)DIM*DIM],  g_woT_l[(size_t)DIM*DIM];
__device__ __nv_bfloat16 g_w1T_h[(size_t)HID*DIM],  g_w1T_l[(size_t)HID*DIM];
__device__ __nv_bfloat16 g_w2T_h[(size_t)HID*DIM],  g_w2T_l[(size_t)HID*DIM];
__device__ __nv_bfloat16 g_w3T_h[(size_t)DIM*HID],  g_w3T_l[(size_t)DIM*HID];
__device__ __nv_bfloat16 g_vT_h [(size_t)BB*NKV*DH*TT], g_vT_l[(size_t)BB*NKV*DH*TT];

// ---------------- helpers ----------------
__device__ __forceinline__ uint32_t smem_u32(const void* p) {
    uint32_t a;
    asm("{ .reg .u64 t; cvta.to.shared.u64 t, %1; cvt.u32.u64 %0, t; }" : "=r"(a) : "l"(p));
    return a;
}

__device__ __forceinline__ void ldsm_x4(uint32_t& r0, uint32_t& r1, uint32_t& r2, uint32_t& r3,
                                        uint32_t addr) {
    asm volatile("ldmatrix.sync.aligned.m8n8.x4.shared.b16 {%0,%1,%2,%3}, [%4];"
                 : "=r"(r0), "=r"(r1), "=r"(r2), "=r"(r3) : "r"(addr));
}

__device__ __forceinline__ void mma16(float* d, const uint32_t* a, const uint32_t* b) {
    asm volatile(
        "mma.sync.aligned.m16n8k16.row.col.f32.bf16.bf16.f32 "
        "{%0,%1,%2,%3},{%4,%5,%6,%7},{%8,%9},{%0,%1,%2,%3};"
        : "+f"(d[0]), "+f"(d[1]), "+f"(d[2]), "+f"(d[3])
        : "r"(a[0]), "r"(a[1]), "r"(a[2]), "r"(a[3]), "r"(b[0]), "r"(b[1]));
}

__device__ __forceinline__ void split_bf16(float x, __nv_bfloat16& h, __nv_bfloat16& l) {
    h = __float2bfloat16_rn(x);
    l = __float2bfloat16_rn(x - __bfloat162float(h));
}

// ---------------- bf16x3 tensor-core GEMM: C[128x128] = A * B^T (+R) -------
// A: fp32 [M,K] row-major.
// B_F32=true : B = Bf fp32 [N,K] row-major (split on load).
// B_F32=false: B = BH/BL bf16 hi/lo [N,K] row-major.
template<bool B_F32>
__device__ void gemm_body(const float* __restrict__ A, int lda,
                          const float* __restrict__ Bf,
                          const __nv_bfloat16* __restrict__ BH,
                          const __nv_bfloat16* __restrict__ BL, int ldb,
                          float* __restrict__ C, int ldc,
                          const float* __restrict__ R, int K,
                          int bm, int bn) {
    __shared__ __nv_bfloat16 Ah[128][SKP], Al[128][SKP];
    __shared__ __nv_bfloat16 Bh[128][SKP], Bl[128][SKP];

    const int tid  = threadIdx.x;
    const int lane = tid & 31;
    const int wid  = tid >> 5;
    const int wr   = wid >> 1;       // 0..3  rows wr*32
    const int wc   = wid & 1;        // 0..1  cols wc*64
    const int g    = lane >> 2;
    const int t    = lane & 3;

    // A/fp32-B loader: row = it*32 + (tid>>3), col4 = (tid&7)*4
    const int lr = tid >> 3, lc = (tid & 7) * 4;
    // bf16-B loader: row = it*64 + (tid>>2), col8 = (tid&3)*8
    const int br = tid >> 2, bc = (tid & 3) * 8;

    const float* Arow = A + (size_t)bm * lda;

    float4 pa[4], pbf[4];
    uint4  pbh[2], pbl[2];

    // ---- prefetch k0 = 0 ----
    #pragma unroll
    for (int it = 0; it < 4; it++)
        pa[it] = *(const float4*)(Arow + (size_t)(it*32 + lr) * lda + lc);
    if (B_F32) {
        #pragma unroll
        for (int it = 0; it < 4; it++)
            pbf[it] = *(const float4*)(Bf + (size_t)(bn + it*32 + lr) * ldb + lc);
    } else {
        #pragma unroll
        for (int it = 0; it < 2; it++) {
            pbh[it] = *(const uint4*)(BH + (size_t)(bn + it*64 + br) * ldb + bc);
            pbl[it] = *(const uint4*)(BL + (size_t)(bn + it*64 + br) * ldb + bc);
        }
    }

    float acc[2][8][4];
    #pragma unroll
    for (int m = 0; m < 2; m++)
        #pragma unroll
        for (int n = 0; n < 8; n++)
            #pragma unroll
            for (int i = 0; i < 4; i++) acc[m][n][i] = 0.f;

    const int NB = K / BK;
    for (int i = 0; i < NB; i++) {
        // ---- store prefetched tile to smem (hi/lo split) ----
        #pragma unroll
        for (int it = 0; it < 4; it++) {
            float v[4] = {pa[it].x, pa[it].y, pa[it].z, pa[it].w};
            #pragma unroll
            for (int j = 0; j < 4; j++)
                split_bf16(v[j], Ah[it*32 + lr][lc + j], Al[it*32 + lr][lc + j]);
        }
        if (B_F32) {
            #pragma unroll
            for (int it = 0; it < 4; it++) {
                float v[4] = {pbf[it].x, pbf[it].y, pbf[it].z, pbf[it].w};
                #pragma unroll
                for (int j = 0; j < 4; j++)
                    split_bf16(v[j], Bh[it*32 + lr][lc + j], Bl[it*32 + lr][lc + j]);
            }
        } else {
            #pragma unroll
            for (int it = 0; it < 2; it++) {
                *(uint4*)&Bh[it*64 + br][bc] = pbh[it];
                *(uint4*)&Bl[it*64 + br][bc] = pbl[it];
            }
        }
        __syncthreads();

        // ---- prefetch next ----
        if (i + 1 < NB) {
            const int kn = (i + 1) * BK;
            #pragma unroll
            for (int it = 0; it < 4; it++)
                pa[it] = *(const float4*)(Arow + (size_t)(it*32 + lr) * lda + kn + lc);
            if (B_F32) {
                #pragma unroll
                for (int it = 0; it < 4; it++)
                    pbf[it] = *(const float4*)(Bf + (size_t)(bn + it*32 + lr) * ldb + kn + lc);
            } else {
                #pragma unroll
                for (int it = 0; it < 2; it++) {
                    pbh[it] = *(const uint4*)(BH + (size_t)(bn + it*64 + br) * ldb + kn + bc);
                    pbl[it] = *(const uint4*)(BL + (size_t)(bn + it*64 + br) * ldb + kn + bc);
                }
            }
        }

        // ---- compute: 2 x k16 steps ----
        #pragma unroll
        for (int kk = 0; kk < BK; kk += 16) {
            const int acol = kk + ((lane >> 4) << 3);
            uint32_t ah[2][4], al[2][4];
            #pragma unroll
            for (int m = 0; m < 2; m++) {
                const int row0 = wr*32 + m*16 + (lane & 15);
                ldsm_x4(ah[m][0], ah[m][1], ah[m][2], ah[m][3], smem_u32(&Ah[row0][acol]));
                ldsm_x4(al[m][0], al[m][1], al[m][2], al[m][3], smem_u32(&Al[row0][acol]));
            }
            #pragma unroll
            for (int nt = 0; nt < 4; nt++) {
                const int n0 = wc*64 + nt*16 + (lane & 15);
                uint32_t rh[4], rl[4];
                ldsm_x4(rh[0], rh[1], rh[2], rh[3], smem_u32(&Bh[n0][acol]));
                ldsm_x4(rl[0], rl[1], rl[2], rl[3], smem_u32(&Bl[n0][acol]));
                uint32_t bh0[2] = {rh[0], rh[2]}, bh1[2] = {rh[1], rh[3]};
                uint32_t bl0[2] = {rl[0], rl[2]}, bl1[2] = {rl[1], rl[3]};
                #pragma unroll
                for (int m = 0; m < 2; m++) {
                    mma16(acc[m][nt*2],   ah[m], bh0);
                    mma16(acc[m][nt*2],   ah[m], bl0);
                    mma16(acc[m][nt*2],   al[m], bh0);
                    mma16(acc[m][nt*2+1], ah[m], bh1);
                    mma16(acc[m][nt*2+1], ah[m], bl1);
                    mma16(acc[m][nt*2+1], al[m], bh1);
                }
            }
        }
        __syncthreads();
    }

    // ---- epilogue ----
    #pragma unroll
    for (int m = 0; m < 2; m++) {
        const int row = bm + wr*32 + m*16 + g;
        #pragma unroll
        for (int n = 0; n < 8; n++) {
            const int col = bn + wc*64 + n*8 + t*2;
            size_t o0 = (size_t)row       * ldc + col;
            size_t o1 = (size_t)(row + 8) * ldc + col;
            float2 v0 = make_float2(acc[m][n][0], acc[m][n][1]);
            float2 v1 = make_float2(acc[m][n][2], acc[m][n][3]);
            if (R) {
                float2 r0 = *(const float2*)(R + o0);
                float2 r1 = *(const float2*)(R + o1);
                v0.x += r0.x; v0.y += r0.y;
                v1.x += r1.x; v1.y += r1.y;
            }
            *(float2*)(C + o0) = v0;
            *(float2*)(C + o1) = v1;
        }
    }
}

// ---------------- GEMM kernel wrappers ----------------
__global__ void __launch_bounds__(256, 2)
k_mma_w(const float* __restrict__ A, int lda,
        const __nv_bfloat16* __restrict__ BH, const __nv_bfloat16* __restrict__ BL, int ldb,
        float* __restrict__ C, int ldc, const float* __restrict__ R, int K) {
    gemm_body<false>(A, lda, nullptr, BH, BL, ldb, C, ldc, R, K,
                     blockIdx.y * 128, blockIdx.x * 128);
}

__global__ void __launch_bounds__(256, 2)
k_mma_qk(const float* __restrict__ q, const float* __restrict__ kk, float* __restrict__ s) {
    if (blockIdx.x > blockIdx.y) return;   // causal: fully masked tile
    int z = blockIdx.z;
    int b = z >> 4, h = z & 15, kv = h >> 2;
    gemm_body<true>(q + (size_t)b*TT*DIM + h*DH, DIM,
                    kk + (size_t)b*TT*KVD + kv*DH, nullptr, nullptr, KVD,
                    s + (size_t)z*TT*TT, TT, nullptr, DH,
                    blockIdx.y * 128, blockIdx.x * 128);
}

__global__ void __launch_bounds__(256, 2)
k_mma_pv(const float* __restrict__ s, const __nv_bfloat16* __restrict__ vth,
         const __nv_bfloat16* __restrict__ vtl, float* __restrict__ y) {
    int z = blockIdx.z;
    int b = z >> 4, h = z & 15, kv = h >> 2;
    size_t voff = (size_t)(b*NKV + kv) * DH * TT;
    gemm_body<false>(s + (size_t)z*TT*TT, TT,
                     nullptr, vth + voff, vtl + voff, TT,
                     y + (size_t)b*TT*DIM + h*DH, DIM, nullptr, TT,
                     blockIdx.y * 128, 0);
}

// ---------------- transpose+convert: W[K][N] fp32 -> WT hi/lo [N][K] bf16 ----
__global__ void k_transp_w(const float* __restrict__ src, int K, int N,
                           __nv_bfloat16* __restrict__ dh, __nv_bfloat16* __restrict__ dl) {
    __shared__ float t[32][33];
    int n0 = blockIdx.x*32, k0 = blockIdx.y*32;
    int tx = threadIdx.x, ty = threadIdx.y;
    #pragma unroll
    for (int r = 0; r < 4; r++)
        t[ty + r*8][tx] = src[(size_t)(k0 + ty + r*8)*N + n0 + tx];
    __syncthreads();
    #pragma unroll
    for (int r = 0; r < 4; r++) {
        int n = n0 + ty + r*8, k = k0 + tx;
        float x = t[tx][ty + r*8];
        __nv_bfloat16 h, l;
        split_bf16(x, h, l);
        dh[(size_t)n*K + k] = h;
        dl[(size_t)n*K + k] = l;
    }
}

// V [b][t][kv*128+dh] -> VT hi/lo [b][kv][dh][t]
__global__ void k_transp_v(const float* __restrict__ v,
                           __nv_bfloat16* __restrict__ dh, __nv_bfloat16* __restrict__ dl) {
    __shared__ float t[32][33];
    int z = blockIdx.z;                  // b*NKV+kv
    int b = z >> 2, kv = z & 3;
    int d0 = blockIdx.x*32, t0 = blockIdx.y*32;
    int tx = threadIdx.x, ty = threadIdx.y;
    #pragma unroll
    for (int r = 0; r < 4; r++)
        t[ty + r*8][tx] = v[((size_t)b*TT + t0 + ty + r*8)*KVD + kv*DH + d0 + tx];
    __syncthreads();
    #pragma unroll
    for (int r = 0; r < 4; r++) {
        int dd = d0 + ty + r*8, tt2 = t0 + tx;
        float x = t[tx][ty + r*8];
        __nv_bfloat16 h, l;
        split_bf16(x, h, l);
        size_t o = ((size_t)z*DH + dd)*TT + tt2;
        dh[o] = h;
        dl[o] = l;
    }
}

// ---------------- reductions ----------------
__device__ __forceinline__ float blockReduceSum(float v) {
    __shared__ float sh[32];
    int lane = threadIdx.x & 31, w = threadIdx.x >> 5;
    #pragma unroll
    for (int o = 16; o > 0; o >>= 1) v += __shfl_xor_sync(0xffffffffu, v, o);
    if (lane == 0) sh[w] = v;
    __syncthreads();
    if (w == 0) {
        v = (lane < (int)(blockDim.x >> 5)) ? sh[lane] : 0.f;
        #pragma unroll
        for (int o = 4; o > 0; o >>= 1) v += __shfl_xor_sync(0xffffffffu, v, o);
        if (lane == 0) sh[0] = v;
    }
    __syncthreads();
    float r = sh[0];
    __syncthreads();
    return r;
}
__device__ __forceinline__ float blockReduceMax(float v) {
    __shared__ float sh[32];
    int lane = threadIdx.x & 31, w = threadIdx.x >> 5;
    #pragma unroll
    for (int o = 16; o > 0; o >>= 1) v = fmaxf(v, __shfl_xor_sync(0xffffffffu, v, o));
    if (lane == 0) sh[w] = v;
    __syncthreads();
    if (w == 0) {
        v = (lane < (int)(blockDim.x >> 5)) ? sh[lane] : -3.4e38f;
        #pragma unroll
        for (int o = 4; o > 0; o >>= 1) v = fmaxf(v, __shfl_xor_sync(0xffffffffu, v, o));
        if (lane == 0) sh[0] = v;
    }
    __syncthreads();
    float r = sh[0];
    __syncthreads();
    return r;
}

// ---------------- elementwise kernels ----------------
__global__ void __launch_bounds__(256) k_rmsnorm(const float* __restrict__ x,
                                                 const float* __restrict__ w,
                                                 float* __restrict__ o) {
    const int row = blockIdx.x;
    const float4* xr = (const float4*)(x + (size_t)row * DIM);
    float4 v0 = xr[threadIdx.x];
    float4 v1 = xr[threadIdx.x + 256];
    float ss = v0.x*v0.x + v0.y*v0.y + v0.z*v0.z + v0.w*v0.w
             + v1.x*v1.x + v1.y*v1.y + v1.z*v1.z + v1.w*v1.w;
    ss = blockReduceSum(ss);
    float scale = rsqrtf(ss * (1.0f/DIM) + 1e-5f);
    const float4* wr = (const float4*)w;
    float4* orow = (float4*)(o + (size_t)row * DIM);
    float4 w0 = wr[threadIdx.x], w1v = wr[threadIdx.x + 256];
    float4 r0, r1;
    r0.x = v0.x*scale*w0.x; r0.y = v0.y*scale*w0.y; r0.z = v0.z*scale*w0.z; r0.w = v0.w*scale*w0.w;
    r1.x = v1.x*scale*w1v.x; r1.y = v1.y*scale*w1v.y; r1.z = v1.z*scale*w1v.z; r1.w = v1.w*scale*w1v.w;
    orow[threadIdx.x] = r0;
    orow[threadIdx.x + 256] = r1;
}

__global__ void k_rope(float* __restrict__ X, int nheads, int total) {
    int idx = blockIdx.x * blockDim.x + threadIdx.x;
    if (idx >= total) return;
    int i  = idx & 63;
    int h  = (idx >> 6) % nheads;
    int bt = idx / (64 * nheads);
    int t  = bt & (TT - 1);
    float inv = powf(10000.0f, -(float)i * (1.0f/64.0f));
    float ang = (float)t * inv;
    float s, c;
    sincosf(ang, &s, &c);
    float* base = X + ((size_t)bt * nheads + h) * DH + i;
    float x1v = base[0];
    float x2v = base[64];
    base[0]  = x1v * c - x2v * s;
    base[64] = x1v * s + x2v * c;
}

__global__ void __launch_bounds__(256) k_softmax(float* __restrict__ S) {
    const size_t row = blockIdx.x;
    const int t = blockIdx.x & (TT - 1);
    float* p = S + row * TT;
    const int n = t + 1;
    const float scale = 0.08838834764831845f;
    const int tid = threadIdx.x;
    float v[4];
    float mx = -3.4e38f;
    #pragma unroll
    for (int u = 0; u < 4; u++) {
        int i = tid + u * 256;
        v[u] = (i < n) ? p[i] * scale : -3.4e38f;
        mx = fmaxf(mx, v[u]);
    }
    mx = blockReduceMax(mx);
    float e[4];
    float lsum = 0.f;
    #pragma unroll
    for (int u = 0; u < 4; u++) {
        int i = tid + u * 256;
        e[u] = (i < n) ? __expf(v[u] - mx) : 0.f;
        lsum += e[u];
    }
    float s = blockReduceSum(lsum);
    float inv = 1.0f / s;
    #pragma unroll
    for (int u = 0; u < 4; u++) p[tid + u * 256] = e[u] * inv;
}

__global__ void __launch_bounds__(256) k_silu_mul(float4* __restrict__ h1,
                                                  const float4* __restrict__ h2,
                                                  int n4) {
    int i = blockIdx.x * blockDim.x + threadIdx.x;
    if (i >= n4) return;
    float4 a = h1[i], b = h2[i];
    a.x = a.x / (1.f + expf(-a.x)) * b.x;
    a.y = a.y / (1.f + expf(-a.y)) * b.y;
    a.z = a.z / (1.f + expf(-a.z)) * b.z;
    a.w = a.w / (1.f + expf(-a.w)) * b.w;
    h1[i] = a;
}

// ---------------- launch ----------------
extern "C" void kernel_launch(void* const* d_in, const int* in_sizes, int n_in,
                              void* d_out, int out_size) {
    const float* x   = (const float*)d_in[0];
    const float* anw = (const float*)d_in[1];
    const float* fnw = (const float*)d_in[2];
    const float* wq  = (const float*)d_in[3];
    const float* wk  = (const float*)d_in[4];
    const float* wv  = (const float*)d_in[5];
    const float* wo  = (const float*)d_in[6];
    const float* w1  = (const float*)d_in[7];
    const float* w2  = (const float*)d_in[8];
    const float* w3  = (const float*)d_in[9];
    float* out = (float*)d_out;

    float *a, *q, *k, *v, *s, *y, *x1, *b, *h1, *h2;
    cudaGetSymbolAddress((void**)&a,  g_a);
    cudaGetSymbolAddress((void**)&q,  g_q);
    cudaGetSymbolAddress((void**)&k,  g_k);
    cudaGetSymbolAddress((void**)&v,  g_v);
    cudaGetSymbolAddress((void**)&s,  g_s);
    cudaGetSymbolAddress((void**)&y,  g_y);
    cudaGetSymbolAddress((void**)&x1, g_x1);
    cudaGetSymbolAddress((void**)&b,  g_b);
    cudaGetSymbolAddress((void**)&h1, g_h1);
    cudaGetSymbolAddress((void**)&h2, g_h2);

    __nv_bfloat16 *wqh,*wql,*wkh,*wkl,*wvh,*wvl,*woh,*wol,*w1h,*w1l,*w2h,*w2l,*w3h,*w3l,*vth,*vtl;
    cudaGetSymbolAddress((void**)&wqh, g_wqT_h); cudaGetSymbolAddress((void**)&wql, g_wqT_l);
    cudaGetSymbolAddress((void**)&wkh, g_wkT_h); cudaGetSymbolAddress((void**)&wkl, g_wkT_l);
    cudaGetSymbolAddress((void**)&wvh, g_wvT_h); cudaGetSymbolAddress((void**)&wvl, g_wvT_l);
    cudaGetSymbolAddress((void**)&woh, g_woT_h); cudaGetSymbolAddress((void**)&wol, g_woT_l);
    cudaGetSymbolAddress((void**)&w1h, g_w1T_h); cudaGetSymbolAddress((void**)&w1l, g_w1T_l);
    cudaGetSymbolAddress((void**)&w2h, g_w2T_h); cudaGetSymbolAddress((void**)&w2l, g_w2T_l);
    cudaGetSymbolAddress((void**)&w3h, g_w3T_h); cudaGetSymbolAddress((void**)&w3l, g_w3T_l);
    cudaGetSymbolAddress((void**)&vth, g_vT_h);  cudaGetSymbolAddress((void**)&vtl, g_vT_l);

    dim3 tb(32, 8);
    // weight transposes (bf16 hi/lo, [N][K])
    k_transp_w<<<dim3(DIM/32, DIM/32), tb>>>(wq, DIM, DIM, wqh, wql);
    k_transp_w<<<dim3(KVD/32, DIM/32), tb>>>(wk, DIM, KVD, wkh, wkl);
    k_transp_w<<<dim3(KVD/32, DIM/32), tb>>>(wv, DIM, KVD, wvh, wvl);
    k_transp_w<<<dim3(DIM/32, DIM/32), tb>>>(wo, DIM, DIM, woh, wol);
    k_transp_w<<<dim3(HID/32, DIM/32), tb>>>(w1, DIM, HID, w1h, w1l);
    k_transp_w<<<dim3(HID/32, DIM/32), tb>>>(w2, DIM, HID, w2h, w2l);
    k_transp_w<<<dim3(DIM/32, HID/32), tb>>>(w3, HID, DIM, w3h, w3l);

    // 1. a = rmsnorm(x)
    k_rmsnorm<<<BT, 256>>>(x, anw, a);
    // 2-4. qkv projections
    k_mma_w<<<dim3(DIM/128, BT/128), 256>>>(a, DIM, wqh, wql, DIM, q, DIM, nullptr, DIM);
    k_mma_w<<<dim3(KVD/128, BT/128), 256>>>(a, DIM, wkh, wkl, DIM, k, KVD, nullptr, DIM);
    k_mma_w<<<dim3(KVD/128, BT/128), 256>>>(a, DIM, wvh, wvl, DIM, v, KVD, nullptr, DIM);
    // 5-6. rope
    k_rope<<<(BT*NH*64)/256, 256>>>(q, NH, BT*NH*64);
    k_rope<<<(BT*NKV*64)/256, 256>>>(k, NKV, BT*NKV*64);
    // 6b. V transpose -> bf16 hi/lo [b][kv][dh][t]
    k_transp_v<<<dim3(DH/32, TT/32, BB*NKV), tb>>>(v, vth, vtl);
    // 7. scores = Q @ K^T (causal skip)
    k_mma_qk<<<dim3(TT/128, TT/128, BB*NH), 256>>>(q, k, s);
    // 8. softmax
    k_softmax<<<BB*NH*TT, 256>>>(s);
    // 9. y = P @ V
    k_mma_pv<<<dim3(1, TT/128, BB*NH), 256>>>(s, vth, vtl, y);
    // 10. x1 = x + y @ wo
    k_mma_w<<<dim3(DIM/128, BT/128), 256>>>(y, DIM, woh, wol, DIM, x1, DIM, x, DIM);
    // 11. b = rmsnorm(x1)
    k_rmsnorm<<<BT, 256>>>(x1, fnw, b);
    // 12-13. MLP up
    k_mma_w<<<dim3(HID/128, BT/128), 256>>>(b, DIM, w1h, w1l, DIM, h1, HID, nullptr, DIM);
    k_mma_w<<<dim3(HID/128, BT/128), 256>>>(b, DIM, w2h, w2l, DIM, h2, HID, nullptr, DIM);
    // 14. silu
    {
        int n4 = (int)((size_t)BT * HID / 4);
        k_silu_mul<<<(n4 + 255) / 256, 256>>>((float4*)h1, (const float4*)h2, n4);
    }
    // 15. out = x1 + h1 @ w3
    k_mma_w<<<dim3(DIM/128, BT/128), 256>>>(h1, HID, w3h, w3l, HID, out, DIM, x1, HID);
}